// round 2
// baseline (speedup 1.0000x reference)
#include <cuda_runtime.h>
#include <cuda_fp16.h>
#include <cstdint>

#define N_EDGES  2000000
#define NUM_SEGS 500000
#define HID      128
#define NRB      4
#define TILE_M   256
#define NTILES   ((N_EDGES + TILE_M - 1) / TILE_M)   /* 7813, last tile partial (128 rows) */
#define NTHREADS 512
#define WSTRIDE  136                  /* halves per W row: 128 + 8 pad -> conflict-free ldmatrix */
#define RMS_EPS  1.1920928955078125e-07f

/* SMEM layout (bytes) */
#define OFF_W     0
#define SZ_W      (NRB * HID * WSTRIDE * 2)          /* 139264 */
#define OFF_WINB  (OFF_W + SZ_W)                     /* float4[128] */
#define OFF_BRES  (OFF_WINB + HID * 16)              /* float[4*128] */
#define OFF_WOUT  (OFF_BRES + NRB * HID * 4)         /* float[128] */
#define OFF_XS    (OFF_WOUT + HID * 4)               /* float4[256] */
#define SMEM_BYTES (OFF_XS + TILE_M * 16)            /* 147968 */

__device__ float    g_logits[N_EDGES];
__device__ unsigned g_segmax[NUM_SEGS];
__device__ float    g_segsum[NUM_SEGS];

__device__ __forceinline__ unsigned enc_f(float f) {
    unsigned b = __float_as_uint(f);
    return (b & 0x80000000u) ? ~b : (b | 0x80000000u);
}
__device__ __forceinline__ float dec_f(unsigned k) {
    unsigned b = (k & 0x80000000u) ? (k & 0x7FFFFFFFu) : ~k;
    return __uint_as_float(b);
}
__device__ __forceinline__ uint32_t pack_h2(float lo, float hi) {
    __half2 h = __floats2half2_rn(lo, hi);
    return *reinterpret_cast<uint32_t*>(&h);
}
__device__ __forceinline__ void ldsm_x4(uint32_t& r0, uint32_t& r1, uint32_t& r2, uint32_t& r3,
                                        uint32_t addr) {
    asm volatile("ldmatrix.sync.aligned.m8n8.x4.shared.b16 {%0,%1,%2,%3}, [%4];\n"
                 : "=r"(r0), "=r"(r1), "=r"(r2), "=r"(r3) : "r"(addr));
}
__device__ __forceinline__ void mma16816(float* d,
        uint32_t a0, uint32_t a1, uint32_t a2, uint32_t a3,
        uint32_t b0, uint32_t b1) {
    asm volatile("mma.sync.aligned.m16n8k16.row.col.f32.f16.f16.f32 "
                 "{%0,%1,%2,%3}, {%4,%5,%6,%7}, {%8,%9}, {%0,%1,%2,%3};\n"
                 : "+f"(d[0]), "+f"(d[1]), "+f"(d[2]), "+f"(d[3])
                 : "r"(a0), "r"(a1), "r"(a2), "r"(a3), "r"(b0), "r"(b1));
}

__global__ void __launch_bounds__(NTHREADS, 1)
mlp_kernel(const float* __restrict__ ef, const int* __restrict__ ids,
           const float* __restrict__ W_in, const float* __restrict__ b_in,
           const float* __restrict__ rms_w, const float* __restrict__ W_res,
           const float* __restrict__ b_res, const float* __restrict__ W_out,
           const float* __restrict__ b_out)
{
    extern __shared__ char smem[];
    __half* Wh   = (__half*)(smem + OFF_W);
    float4* winb = (float4*)(smem + OFF_WINB);
    float*  brs  = (float*)(smem + OFF_BRES);
    float*  wout = (float*)(smem + OFF_WOUT);
    float4* xs   = (float4*)(smem + OFF_XS);

    const int tid = threadIdx.x;

    /* ---- stage weights once per CTA; fold rms_w (per-k) into W_res ---- */
    for (int idx = tid; idx < NRB * HID * HID; idx += NTHREADS) {
        int i   = idx >> 14;
        int rem = idx & 16383;
        int n   = rem >> 7;
        int k   = rem & 127;
        float w = W_res[idx] * rms_w[i * HID + k];
        Wh[(i * HID + n) * WSTRIDE + k] = __float2half(w);
    }
    for (int c = tid; c < HID; c += NTHREADS) {
        winb[c] = make_float4(W_in[c * 3], W_in[c * 3 + 1], W_in[c * 3 + 2], b_in[c]);
        wout[c] = W_out[c];
    }
    for (int idx = tid; idx < NRB * HID; idx += NTHREADS) brs[idx] = b_res[idx];

    const float bout = b_out[0];
    const int warp = tid >> 5, lane = tid & 31;
    const int q = lane & 3, gid = lane >> 2;

    uint32_t wbase = (uint32_t)__cvta_generic_to_shared(Wh);
    /* ldmatrix.x4 source rows:
       lanes 0-7  : n-tile j,   k halves [0,8)     -> reg0
       lanes 8-15 : n-tile j,   k halves [8,16)    -> reg1
       lanes 16-23: n-tile j+1, k halves [0,8)     -> reg2
       lanes 24-31: n-tile j+1, k halves [8,16)    -> reg3  */
    uint32_t laneB = wbase +
        ((((lane & 7) + ((lane >> 4) & 1) * 8) * WSTRIDE) + ((lane >> 3) & 1) * 8) * 2;

    /* prefetch first tile's input rows */
    float3 xpre = make_float3(0.f, 0.f, 0.f);
    if (tid < TILE_M) {
        long r = (long)blockIdx.x * TILE_M + tid;
        if (r < N_EDGES) xpre = make_float3(ef[r * 3], ef[r * 3 + 1], ef[r * 3 + 2]);
    }

    for (int tile = blockIdx.x; tile < NTILES; tile += gridDim.x) {
        __syncthreads();
        if (tid < TILE_M) xs[tid] = make_float4(xpre.x, xpre.y, xpre.z, 0.f);
        __syncthreads();

        float4 x0 = xs[warp * 16 + gid];
        float4 x1 = xs[warp * 16 + gid + 8];

        /* prefetch next tile while this one computes (hides DRAM latency) */
        {
            int nt = tile + gridDim.x;
            xpre = make_float3(0.f, 0.f, 0.f);
            if (nt < NTILES && tid < TILE_M) {
                long r = (long)nt * TILE_M + tid;
                if (r < N_EDGES)
                    xpre = make_float3(ef[r * 3], ef[r * 3 + 1], ef[r * 3 + 2]);
            }
        }

        /* ---- input layer, directly in C-fragment layout ----
           hc[j][0]=(row gid,   col 8j+2q)  hc[j][1]=(row gid,   col 8j+2q+1)
           hc[j][2]=(row gid+8, col 8j+2q)  hc[j][3]=(row gid+8, col 8j+2q+1) */
        float hc[16][4];
        #pragma unroll
        for (int j = 0; j < 16; j++) {
            float4 w0 = winb[j * 8 + q * 2];
            float4 w1 = winb[j * 8 + q * 2 + 1];
            hc[j][0] = w0.w + x0.x * w0.x + x0.y * w0.y + x0.z * w0.z;
            hc[j][1] = w1.w + x0.x * w1.x + x0.y * w1.y + x0.z * w1.z;
            hc[j][2] = w0.w + x1.x * w0.x + x1.y * w0.y + x1.z * w0.z;
            hc[j][3] = w1.w + x1.x * w1.x + x1.y * w1.y + x1.z * w1.z;
        }

        /* ---- 4 residual blocks, activations never leave registers ---- */
        #pragma unroll
        for (int blk = 0; blk < NRB; blk++) {
            /* RMS statistics on unscaled h; scale applied post-GEMM (linear in rows) */
            float ss0 = 0.f, ss1 = 0.f;
            #pragma unroll
            for (int j = 0; j < 16; j++) {
                ss0 += hc[j][0] * hc[j][0] + hc[j][1] * hc[j][1];
                ss1 += hc[j][2] * hc[j][2] + hc[j][3] * hc[j][3];
            }
            ss0 += __shfl_xor_sync(0xffffffffu, ss0, 1);
            ss0 += __shfl_xor_sync(0xffffffffu, ss0, 2);
            ss1 += __shfl_xor_sync(0xffffffffu, ss1, 1);
            ss1 += __shfl_xor_sync(0xffffffffu, ss1, 2);
            float s0 = rsqrtf(ss0 * (1.f / HID) + RMS_EPS);
            float s1 = rsqrtf(ss1 * (1.f / HID) + RMS_EPS);

            float y[16][4];
            #pragma unroll
            for (int j = 0; j < 16; j++)
                y[j][0] = y[j][1] = y[j][2] = y[j][3] = 0.f;

            uint32_t lb = laneB + blk * (HID * WSTRIDE * 2);
            #pragma unroll
            for (int ks = 0; ks < 8; ks++) {
                /* A fragment (unscaled h) built from C tiles 2ks, 2ks+1 */
                int j0 = 2 * ks, j1 = 2 * ks + 1;
                uint32_t a0 = pack_h2(hc[j0][0], hc[j0][1]);
                uint32_t a1 = pack_h2(hc[j0][2], hc[j0][3]);
                uint32_t a2 = pack_h2(hc[j1][0], hc[j1][1]);
                uint32_t a3 = pack_h2(hc[j1][2], hc[j1][3]);
                #pragma unroll
                for (int j = 0; j < 16; j += 2) {
                    uint32_t b0, b1, b2, b3;
                    ldsm_x4(b0, b1, b2, b3,
                            lb + (uint32_t)((j * 8 * WSTRIDE + ks * 16) * 2));
                    mma16816(y[j],     a0, a1, a2, a3, b0, b1);
                    mma16816(y[j + 1], a0, a1, a2, a3, b2, b3);
                }
            }

            /* epilogue: h += relu(s .* y + b); scale folds into the FFMA */
            const float2* br2 = (const float2*)(brs + blk * HID);
            #pragma unroll
            for (int j = 0; j < 16; j++) {
                float2 bb = br2[j * 4 + q];
                hc[j][0] += fmaxf(fmaf(y[j][0], s0, bb.x), 0.f);
                hc[j][1] += fmaxf(fmaf(y[j][1], s0, bb.y), 0.f);
                hc[j][2] += fmaxf(fmaf(y[j][2], s1, bb.x), 0.f);
                hc[j][3] += fmaxf(fmaf(y[j][3], s1, bb.y), 0.f);
            }
        }

        /* ---- output layer + fused segment-max ---- */
        float a0 = 0.f, a1 = 0.f;
        const float2* w2 = (const float2*)wout;
        #pragma unroll
        for (int j = 0; j < 16; j++) {
            float2 w = w2[j * 4 + q];
            a0 += hc[j][0] * w.x + hc[j][1] * w.y;
            a1 += hc[j][2] * w.x + hc[j][3] * w.y;
        }
        a0 += __shfl_xor_sync(0xffffffffu, a0, 1);
        a0 += __shfl_xor_sync(0xffffffffu, a0, 2);
        a1 += __shfl_xor_sync(0xffffffffu, a1, 1);
        a1 += __shfl_xor_sync(0xffffffffu, a1, 2);
        if (q == 0) {
            long r0 = (long)tile * TILE_M + warp * 16 + gid;
            long r1 = r0 + 8;
            float l0 = a0 + bout, l1 = a1 + bout;
            if (r0 < N_EDGES) {
                g_logits[r0] = l0;
                atomicMax(&g_segmax[ids[r0]], enc_f(l0));
            }
            if (r1 < N_EDGES) {
                g_logits[r1] = l1;
                atomicMax(&g_segmax[ids[r1]], enc_f(l1));
            }
        }
    }
}

__global__ void init_kernel() {
    int i = blockIdx.x * blockDim.x + threadIdx.x;
    if (i < NUM_SEGS) { g_segmax[i] = 0u; g_segsum[i] = 0.f; }
}

__global__ void exp_kernel(const int* __restrict__ ids, float* __restrict__ out) {
    int i = blockIdx.x * blockDim.x + threadIdx.x;
    if (i < N_EDGES) {
        int s = ids[i];
        float m = dec_f(g_segmax[s]);
        float e = expf(g_logits[i] - m);
        out[i] = e;
        atomicAdd(&g_segsum[s], e);
    }
}

__global__ void norm_kernel(const int* __restrict__ ids, float* __restrict__ out) {
    int i = blockIdx.x * blockDim.x + threadIdx.x;
    if (i < N_EDGES) out[i] = out[i] / g_segsum[ids[i]];
}

extern "C" void kernel_launch(void* const* d_in, const int* in_sizes, int n_in,
                              void* d_out, int out_size)
{
    const float* ef    = (const float*)d_in[0];
    const int*   ids   = (const int*)d_in[1];
    const float* W_in  = (const float*)d_in[2];
    const float* b_in  = (const float*)d_in[3];
    const float* rms_w = (const float*)d_in[4];
    const float* W_res = (const float*)d_in[5];
    const float* b_res = (const float*)d_in[6];
    const float* W_out = (const float*)d_in[7];
    const float* b_out = (const float*)d_in[8];
    float* out = (float*)d_out;

    cudaFuncSetAttribute(mlp_kernel, cudaFuncAttributeMaxDynamicSharedMemorySize, SMEM_BYTES);

    int dev = 0, sms = 148;
    cudaGetDevice(&dev);
    cudaDeviceGetAttribute(&sms, cudaDevAttrMultiProcessorCount, dev);
    if (sms <= 0) sms = 148;

    init_kernel<<<(NUM_SEGS + 255) / 256, 256>>>();
    mlp_kernel<<<sms, NTHREADS, SMEM_BYTES>>>(ef, ids, W_in, b_in, rms_w,
                                              W_res, b_res, W_out, b_out);
    exp_kernel<<<(N_EDGES + 255) / 256, 256>>>(ids, out);
    norm_kernel<<<(N_EDGES + 255) / 256, 256>>>(ids, out);
}

// round 3
// speedup vs baseline: 1.2758x; 1.2758x over previous
#include <cuda_runtime.h>
#include <cuda_fp16.h>
#include <cstdint>

#define N_EDGES  2000000
#define NUM_SEGS 500000
#define HID      128
#define NRB      4
#define TILE_M   256
#define NTILES   ((N_EDGES + TILE_M - 1) / TILE_M)   /* 7813, last tile 128 rows */
#define NTHREADS 256
#define WSTRIDE  136                  /* halves per W row: 128 + 8 pad */
#define RMS_EPS  1.1920928955078125e-07f

/* SMEM layout (bytes) */
#define OFF_W     0
#define SZ_W      (NRB * HID * WSTRIDE * 2)          /* 139264 */
#define OFF_WINB  (OFF_W + SZ_W)                     /* float4[128] */
#define OFF_BRES  (OFF_WINB + HID * 16)              /* float[4*128] */
#define OFF_WOUT  (OFF_BRES + NRB * HID * 4)         /* float[128] */
#define OFF_XS    (OFF_WOUT + HID * 4)               /* float4[256] */
#define SMEM_BYTES (OFF_XS + TILE_M * 16)            /* 147968 */

__device__ float    g_logits[N_EDGES];
__device__ unsigned g_segmax[NUM_SEGS];
__device__ float    g_segsum[NUM_SEGS];

__device__ __forceinline__ unsigned enc_f(float f) {
    unsigned b = __float_as_uint(f);
    return (b & 0x80000000u) ? ~b : (b | 0x80000000u);
}
__device__ __forceinline__ float dec_f(unsigned k) {
    unsigned b = (k & 0x80000000u) ? (k & 0x7FFFFFFFu) : ~k;
    return __uint_as_float(b);
}
__device__ __forceinline__ uint32_t pack_h2(float lo, float hi) {
    __half2 h = __floats2half2_rn(lo, hi);
    return *reinterpret_cast<uint32_t*>(&h);
}
__device__ __forceinline__ float2 unpack_h2(uint32_t u) {
    return __half22float2(*reinterpret_cast<__half2*>(&u));
}
__device__ __forceinline__ void ldsm_x4(uint32_t& r0, uint32_t& r1, uint32_t& r2, uint32_t& r3,
                                        uint32_t addr) {
    asm volatile("ldmatrix.sync.aligned.m8n8.x4.shared.b16 {%0,%1,%2,%3}, [%4];\n"
                 : "=r"(r0), "=r"(r1), "=r"(r2), "=r"(r3) : "r"(addr));
}
__device__ __forceinline__ void mma16816(float* d,
        uint32_t a0, uint32_t a1, uint32_t a2, uint32_t a3,
        uint32_t b0, uint32_t b1) {
    asm volatile("mma.sync.aligned.m16n8k16.row.col.f32.f16.f16.f32 "
                 "{%0,%1,%2,%3}, {%4,%5,%6,%7}, {%8,%9}, {%0,%1,%2,%3};\n"
                 : "+f"(d[0]), "+f"(d[1]), "+f"(d[2]), "+f"(d[3])
                 : "r"(a0), "r"(a1), "r"(a2), "r"(a3), "r"(b0), "r"(b1));
}

__global__ void __launch_bounds__(NTHREADS, 1)
mlp_kernel(const float* __restrict__ ef, const int* __restrict__ ids,
           const float* __restrict__ W_in, const float* __restrict__ b_in,
           const float* __restrict__ rms_w, const float* __restrict__ W_res,
           const float* __restrict__ b_res, const float* __restrict__ W_out,
           const float* __restrict__ b_out)
{
    extern __shared__ char smem[];
    __half* Wh   = (__half*)(smem + OFF_W);
    float4* winb = (float4*)(smem + OFF_WINB);
    float*  brs  = (float*)(smem + OFF_BRES);
    float*  wout = (float*)(smem + OFF_WOUT);
    float4* xs   = (float4*)(smem + OFF_XS);

    const int tid = threadIdx.x;

    /* ---- stage weights once per CTA; fold rms_w (per-k) into W_res ---- */
    for (int idx = tid; idx < NRB * HID * HID; idx += NTHREADS) {
        int i   = idx >> 14;
        int rem = idx & 16383;
        int n   = rem >> 7;
        int k   = rem & 127;
        float w = W_res[idx] * rms_w[i * HID + k];
        Wh[(i * HID + n) * WSTRIDE + k] = __float2half(w);
    }
    for (int c = tid; c < HID; c += NTHREADS) {
        winb[c] = make_float4(W_in[c * 3], W_in[c * 3 + 1], W_in[c * 3 + 2], b_in[c]);
        wout[c] = W_out[c];
    }
    for (int idx = tid; idx < NRB * HID; idx += NTHREADS) brs[idx] = b_res[idx];

    const float bout = b_out[0];
    const int warp = tid >> 5, lane = tid & 31;
    const int q = lane & 3, gid = lane >> 2;

    uint32_t wbase = (uint32_t)__cvta_generic_to_shared(Wh);
    /* ldmatrix.x4 rows: lanes 0-7: tile j k[0,8) | 8-15: j k[8,16) |
       16-23: j+1 k[0,8) | 24-31: j+1 k[8,16) */
    uint32_t laneB = wbase +
        ((((lane & 7) + ((lane >> 4) & 1) * 8) * WSTRIDE) + ((lane >> 3) & 1) * 8) * 2;

    /* prefetch first tile's input rows (1 row / thread) */
    float3 xpre = make_float3(0.f, 0.f, 0.f);
    {
        long r = (long)blockIdx.x * TILE_M + tid;
        if (r < N_EDGES) xpre = make_float3(ef[r * 3], ef[r * 3 + 1], ef[r * 3 + 2]);
    }

    for (int tile = blockIdx.x; tile < NTILES; tile += gridDim.x) {
        __syncthreads();
        xs[tid] = make_float4(xpre.x, xpre.y, xpre.z, 0.f);
        __syncthreads();

        /* each warp: rows [warp*32, warp*32+32): sub-tile s2 covers +s2*16 */
        float4 xv[2][2];
        xv[0][0] = xs[warp * 32 + gid];
        xv[0][1] = xs[warp * 32 + gid + 8];
        xv[1][0] = xs[warp * 32 + gid + 16];
        xv[1][1] = xs[warp * 32 + gid + 24];

        /* prefetch next tile while this one computes */
        {
            int nt = tile + gridDim.x;
            xpre = make_float3(0.f, 0.f, 0.f);
            if (nt < NTILES) {
                long r = (long)nt * TILE_M + tid;
                if (r < N_EDGES)
                    xpre = make_float3(ef[r * 3], ef[r * 3 + 1], ef[r * 3 + 2]);
            }
        }

        /* ---- residual stream, packed fp16 A-fragment layout ----
           hp[s2][4*ks+0] = (row gid,   cols 16ks+2q, +1)
           hp[s2][4*ks+1] = (row gid+8, cols 16ks+2q, +1)
           hp[s2][4*ks+2] = (row gid,   cols 16ks+8+2q, +1)
           hp[s2][4*ks+3] = (row gid+8, cols 16ks+8+2q, +1)      */
        uint32_t hp[2][32];
        float ssl[2][2];
        ssl[0][0] = ssl[0][1] = ssl[1][0] = ssl[1][1] = 0.f;

        /* ---- input layer straight into packed layout ---- */
        #pragma unroll
        for (int j = 0; j < 16; j++) {
            float4 w0 = winb[j * 8 + q * 2];
            float4 w1 = winb[j * 8 + q * 2 + 1];
            int i0 = 4 * (j >> 1) + (j & 1) * 2;
            #pragma unroll
            for (int s2 = 0; s2 < 2; s2++) {
                float4 xa = xv[s2][0], xb = xv[s2][1];
                float n0 = w0.w + xa.x * w0.x + xa.y * w0.y + xa.z * w0.z;
                float n1 = w1.w + xa.x * w1.x + xa.y * w1.y + xa.z * w1.z;
                float n2 = w0.w + xb.x * w0.x + xb.y * w0.y + xb.z * w0.z;
                float n3 = w1.w + xb.x * w1.x + xb.y * w1.y + xb.z * w1.z;
                hp[s2][i0]     = pack_h2(n0, n1);
                hp[s2][i0 + 1] = pack_h2(n2, n3);
                ssl[s2][0] += n0 * n0 + n1 * n1;
                ssl[s2][1] += n2 * n2 + n3 * n3;
            }
        }

        /* ---- 4 residual blocks ---- */
        #pragma unroll 1
        for (int blk = 0; blk < NRB; blk++) {
            float sc[2][2];
            #pragma unroll
            for (int s2 = 0; s2 < 2; s2++)
                #pragma unroll
                for (int g = 0; g < 2; g++) {
                    float v = ssl[s2][g];
                    v += __shfl_xor_sync(0xffffffffu, v, 1);
                    v += __shfl_xor_sync(0xffffffffu, v, 2);
                    sc[s2][g] = rsqrtf(v * (1.f / HID) + RMS_EPS);
                }

            float y[2][16][4];
            #pragma unroll
            for (int s2 = 0; s2 < 2; s2++)
                #pragma unroll
                for (int j = 0; j < 16; j++)
                    y[s2][j][0] = y[s2][j][1] = y[s2][j][2] = y[s2][j][3] = 0.f;

            uint32_t lb = laneB + blk * (HID * WSTRIDE * 2);
            #pragma unroll
            for (int ks = 0; ks < 8; ks++) {
                #pragma unroll
                for (int j = 0; j < 16; j += 2) {
                    uint32_t b0, b1, b2, b3;
                    ldsm_x4(b0, b1, b2, b3,
                            lb + (uint32_t)((j * 8 * WSTRIDE + ks * 16) * 2));
                    /* 4 MMAs per ldmatrix.x4: B reused across 2 j-tiles x 2 m-subtiles */
                    mma16816(y[0][j],     hp[0][4*ks], hp[0][4*ks+1], hp[0][4*ks+2], hp[0][4*ks+3], b0, b1);
                    mma16816(y[0][j + 1], hp[0][4*ks], hp[0][4*ks+1], hp[0][4*ks+2], hp[0][4*ks+3], b2, b3);
                    mma16816(y[1][j],     hp[1][4*ks], hp[1][4*ks+1], hp[1][4*ks+2], hp[1][4*ks+3], b0, b1);
                    mma16816(y[1][j + 1], hp[1][4*ks], hp[1][4*ks+1], hp[1][4*ks+2], hp[1][4*ks+3], b2, b3);
                }
            }

            /* epilogue: h += relu(s .* y + b); recompute ss for next block */
            const float2* br2 = (const float2*)(brs + blk * HID);
            float nss[2][2];
            nss[0][0] = nss[0][1] = nss[1][0] = nss[1][1] = 0.f;
            #pragma unroll
            for (int j = 0; j < 16; j++) {
                float2 bb = br2[j * 4 + q];
                int i0 = 4 * (j >> 1) + (j & 1) * 2;
                #pragma unroll
                for (int s2 = 0; s2 < 2; s2++) {
                    float2 hA = unpack_h2(hp[s2][i0]);
                    float2 hB = unpack_h2(hp[s2][i0 + 1]);
                    float n0 = hA.x + fmaxf(fmaf(y[s2][j][0], sc[s2][0], bb.x), 0.f);
                    float n1 = hA.y + fmaxf(fmaf(y[s2][j][1], sc[s2][0], bb.y), 0.f);
                    float n2 = hB.x + fmaxf(fmaf(y[s2][j][2], sc[s2][1], bb.x), 0.f);
                    float n3 = hB.y + fmaxf(fmaf(y[s2][j][3], sc[s2][1], bb.y), 0.f);
                    hp[s2][i0]     = pack_h2(n0, n1);
                    hp[s2][i0 + 1] = pack_h2(n2, n3);
                    nss[s2][0] += n0 * n0 + n1 * n1;
                    nss[s2][1] += n2 * n2 + n3 * n3;
                }
            }
            ssl[0][0] = nss[0][0]; ssl[0][1] = nss[0][1];
            ssl[1][0] = nss[1][0]; ssl[1][1] = nss[1][1];
        }

        /* ---- output layer + fused segment-max ---- */
        const float2* w2 = (const float2*)wout;
        #pragma unroll
        for (int s2 = 0; s2 < 2; s2++) {
            float a0 = 0.f, a1 = 0.f;
            #pragma unroll
            for (int j = 0; j < 16; j++) {
                float2 w = w2[j * 4 + q];
                int i0 = 4 * (j >> 1) + (j & 1) * 2;
                float2 hA = unpack_h2(hp[s2][i0]);
                float2 hB = unpack_h2(hp[s2][i0 + 1]);
                a0 += hA.x * w.x + hA.y * w.y;
                a1 += hB.x * w.x + hB.y * w.y;
            }
            a0 += __shfl_xor_sync(0xffffffffu, a0, 1);
            a0 += __shfl_xor_sync(0xffffffffu, a0, 2);
            a1 += __shfl_xor_sync(0xffffffffu, a1, 1);
            a1 += __shfl_xor_sync(0xffffffffu, a1, 2);
            if (q == 0) {
                long r0 = (long)tile * TILE_M + warp * 32 + s2 * 16 + gid;
                long r1 = r0 + 8;
                float l0 = a0 + bout, l1 = a1 + bout;
                if (r0 < N_EDGES) {
                    g_logits[r0] = l0;
                    atomicMax(&g_segmax[ids[r0]], enc_f(l0));
                }
                if (r1 < N_EDGES) {
                    g_logits[r1] = l1;
                    atomicMax(&g_segmax[ids[r1]], enc_f(l1));
                }
            }
        }
    }
}

__global__ void init_kernel() {
    int i = blockIdx.x * blockDim.x + threadIdx.x;
    if (i < NUM_SEGS) { g_segmax[i] = 0u; g_segsum[i] = 0.f; }
}

__global__ void exp_kernel(const int* __restrict__ ids, float* __restrict__ out) {
    int i = blockIdx.x * blockDim.x + threadIdx.x;
    if (i < N_EDGES) {
        int s = ids[i];
        float m = dec_f(g_segmax[s]);
        float e = expf(g_logits[i] - m);
        out[i] = e;
        atomicAdd(&g_segsum[s], e);
    }
}

__global__ void norm_kernel(const int* __restrict__ ids, float* __restrict__ out) {
    int i = blockIdx.x * blockDim.x + threadIdx.x;
    if (i < N_EDGES) out[i] = out[i] / g_segsum[ids[i]];
}

extern "C" void kernel_launch(void* const* d_in, const int* in_sizes, int n_in,
                              void* d_out, int out_size)
{
    const float* ef    = (const float*)d_in[0];
    const int*   ids   = (const int*)d_in[1];
    const float* W_in  = (const float*)d_in[2];
    const float* b_in  = (const float*)d_in[3];
    const float* rms_w = (const float*)d_in[4];
    const float* W_res = (const float*)d_in[5];
    const float* b_res = (const float*)d_in[6];
    const float* W_out = (const float*)d_in[7];
    const float* b_out = (const float*)d_in[8];
    float* out = (float*)d_out;

    cudaFuncSetAttribute(mlp_kernel, cudaFuncAttributeMaxDynamicSharedMemorySize, SMEM_BYTES);

    int dev = 0, sms = 148;
    cudaGetDevice(&dev);
    cudaDeviceGetAttribute(&sms, cudaDevAttrMultiProcessorCount, dev);
    if (sms <= 0) sms = 148;

    init_kernel<<<(NUM_SEGS + 255) / 256, 256>>>();
    mlp_kernel<<<sms, NTHREADS, SMEM_BYTES>>>(ef, ids, W_in, b_in, rms_w,
                                              W_res, b_res, W_out, b_out);
    exp_kernel<<<(N_EDGES + 255) / 256, 256>>>(ids, out);
    norm_kernel<<<(N_EDGES + 255) / 256, 256>>>(ids, out);
}

// round 4
// speedup vs baseline: 1.3941x; 1.0928x over previous
#include <cuda_runtime.h>
#include <cuda_fp16.h>
#include <cstdint>

#define N_EDGES  2000000
#define NUM_SEGS 500000
#define HID      128
#define NRB      4
#define TILE_M   256
#define NTILES   ((N_EDGES + TILE_M - 1) / TILE_M)   /* 7813, last tile 128 rows */
#define NTHREADS 256
#define WSTRIDE  136                  /* halves per W row: 128 + 8 pad */
#define RMS_EPS  1.1920928955078125e-07f

/* SMEM layout (bytes) */
#define OFF_W     0
#define SZ_W      (NRB * HID * WSTRIDE * 2)          /* 139264 */
#define OFF_WINB  (OFF_W + SZ_W)                     /* float4[128] */
#define OFF_BRESH (OFF_WINB + HID * 16)              /* half2[4*64]  */
#define OFF_WOUT  (OFF_BRESH + NRB * 64 * 4)         /* float[128] */
#define OFF_XS    (OFF_WOUT + HID * 4)               /* float4[256] */
#define SMEM_BYTES (OFF_XS + TILE_M * 16)

__device__ float    g_logits[N_EDGES];
__device__ unsigned g_segmax[NUM_SEGS];
__device__ float    g_segsum[NUM_SEGS];

__device__ __forceinline__ unsigned enc_f(float f) {
    unsigned b = __float_as_uint(f);
    return (b & 0x80000000u) ? ~b : (b | 0x80000000u);
}
__device__ __forceinline__ float dec_f(unsigned k) {
    unsigned b = (k & 0x80000000u) ? (k & 0x7FFFFFFFu) : ~k;
    return __uint_as_float(b);
}
__device__ __forceinline__ uint32_t pack_h2(float lo, float hi) {
    __half2 h = __floats2half2_rn(lo, hi);
    return *reinterpret_cast<uint32_t*>(&h);
}
__device__ __forceinline__ float2 unpack_h2(uint32_t u) {
    return __half22float2(*reinterpret_cast<__half2*>(&u));
}
__device__ __forceinline__ uint32_t hadd2_u(uint32_t a, uint32_t b) {
    __half2 r = __hadd2(*reinterpret_cast<__half2*>(&a), *reinterpret_cast<__half2*>(&b));
    return *reinterpret_cast<uint32_t*>(&r);
}
__device__ __forceinline__ uint32_t hmax2z_u(uint32_t a) {
    __half2 z = __float2half2_rn(0.f);
    __half2 r = __hmax2(*reinterpret_cast<__half2*>(&a), z);
    return *reinterpret_cast<uint32_t*>(&r);
}
__device__ __forceinline__ uint32_t hfma2_u(uint32_t a, uint32_t b, uint32_t c) {
    __half2 r = __hfma2(*reinterpret_cast<__half2*>(&a),
                        *reinterpret_cast<__half2*>(&b),
                        *reinterpret_cast<__half2*>(&c));
    return *reinterpret_cast<uint32_t*>(&r);
}
__device__ __forceinline__ void ldsm_x4(uint32_t& r0, uint32_t& r1, uint32_t& r2, uint32_t& r3,
                                        uint32_t addr) {
    asm volatile("ldmatrix.sync.aligned.m8n8.x4.shared.b16 {%0,%1,%2,%3}, [%4];\n"
                 : "=r"(r0), "=r"(r1), "=r"(r2), "=r"(r3) : "r"(addr));
}
__device__ __forceinline__ void mma16816(float* d,
        uint32_t a0, uint32_t a1, uint32_t a2, uint32_t a3,
        uint32_t b0, uint32_t b1) {
    asm volatile("mma.sync.aligned.m16n8k16.row.col.f32.f16.f16.f32 "
                 "{%0,%1,%2,%3}, {%4,%5,%6,%7}, {%8,%9}, {%0,%1,%2,%3};\n"
                 : "+f"(d[0]), "+f"(d[1]), "+f"(d[2]), "+f"(d[3])
                 : "r"(a0), "r"(a1), "r"(a2), "r"(a3), "r"(b0), "r"(b1));
}

__global__ void __launch_bounds__(NTHREADS, 1)
mlp_kernel(const float* __restrict__ ef, const int* __restrict__ ids,
           const float* __restrict__ W_in, const float* __restrict__ b_in,
           const float* __restrict__ rms_w, const float* __restrict__ W_res,
           const float* __restrict__ b_res, const float* __restrict__ W_out,
           const float* __restrict__ b_out)
{
    extern __shared__ char smem[];
    __half*   Wh   = (__half*)(smem + OFF_W);
    float4*   winb = (float4*)(smem + OFF_WINB);
    uint32_t* brsh = (uint32_t*)(smem + OFF_BRESH);
    float*    wout = (float*)(smem + OFF_WOUT);
    float4*   xs   = (float4*)(smem + OFF_XS);

    const int tid = threadIdx.x;

    /* ---- stage weights once per CTA; fold rms_w (per-k) into W_res ---- */
    for (int idx = tid; idx < NRB * HID * HID; idx += NTHREADS) {
        int i   = idx >> 14;
        int rem = idx & 16383;
        int n   = rem >> 7;
        int k   = rem & 127;
        float w = W_res[idx] * rms_w[i * HID + k];
        Wh[(i * HID + n) * WSTRIDE + k] = __float2half(w);
    }
    for (int c = tid; c < HID; c += NTHREADS) {
        winb[c] = make_float4(W_in[c * 3], W_in[c * 3 + 1], W_in[c * 3 + 2], b_in[c]);
        wout[c] = W_out[c];
    }
    /* bias as half2 pairs: brsh[blk*64 + c2] = (b[2c2], b[2c2+1]) */
    for (int idx = tid; idx < NRB * 64; idx += NTHREADS) {
        int i = idx >> 6, c2 = idx & 63;
        brsh[idx] = pack_h2(b_res[i * HID + 2 * c2], b_res[i * HID + 2 * c2 + 1]);
    }

    const float bout = b_out[0];
    const int warp = tid >> 5, lane = tid & 31;
    const int q = lane & 3, gid = lane >> 2;

    uint32_t wbase = (uint32_t)__cvta_generic_to_shared(Wh);
    uint32_t laneB = wbase +
        ((((lane & 7) + ((lane >> 4) & 1) * 8) * WSTRIDE) + ((lane >> 3) & 1) * 8) * 2;

    /* prefetch first tile's input rows (1 row / thread) */
    float3 xpre = make_float3(0.f, 0.f, 0.f);
    {
        long r = (long)blockIdx.x * TILE_M + tid;
        if (r < N_EDGES) xpre = make_float3(ef[r * 3], ef[r * 3 + 1], ef[r * 3 + 2]);
    }

    for (int tile = blockIdx.x; tile < NTILES; tile += gridDim.x) {
        __syncthreads();
        xs[tid] = make_float4(xpre.x, xpre.y, xpre.z, 0.f);
        __syncthreads();

        float4 xv[2][2];
        xv[0][0] = xs[warp * 32 + gid];
        xv[0][1] = xs[warp * 32 + gid + 8];
        xv[1][0] = xs[warp * 32 + gid + 16];
        xv[1][1] = xs[warp * 32 + gid + 24];

        /* prefetch next tile while this one computes */
        {
            int nt = tile + gridDim.x;
            xpre = make_float3(0.f, 0.f, 0.f);
            if (nt < NTILES) {
                long r = (long)nt * TILE_M + tid;
                if (r < N_EDGES)
                    xpre = make_float3(ef[r * 3], ef[r * 3 + 1], ef[r * 3 + 2]);
            }
        }

        /* ---- residual stream, packed fp16 A-fragment layout ----
           hp[s2][4*ks+0]=(row gid,  cols 16ks+2q,+1)  [4*ks+1]=(row gid+8, same)
           hp[s2][4*ks+2]=(row gid,  cols 16ks+8+2q,+1)[4*ks+3]=(row gid+8, same) */
        uint32_t hp[2][32];
        float ssf[2][2];   /* f32 sum-of-squares feed for the NEXT scale */
        ssf[0][0] = ssf[0][1] = ssf[1][0] = ssf[1][1] = 0.f;

        /* ---- input layer straight into packed layout (f32 math) ---- */
        #pragma unroll
        for (int j = 0; j < 16; j++) {
            float4 w0 = winb[j * 8 + q * 2];
            float4 w1 = winb[j * 8 + q * 2 + 1];
            int i0 = 4 * (j >> 1) + (j & 1) * 2;
            #pragma unroll
            for (int s2 = 0; s2 < 2; s2++) {
                float4 xa = xv[s2][0], xb = xv[s2][1];
                float n0 = w0.w + xa.x * w0.x + xa.y * w0.y + xa.z * w0.z;
                float n1 = w1.w + xa.x * w1.x + xa.y * w1.y + xa.z * w1.z;
                float n2 = w0.w + xb.x * w0.x + xb.y * w0.y + xb.z * w0.z;
                float n3 = w1.w + xb.x * w1.x + xb.y * w1.y + xb.z * w1.z;
                hp[s2][i0]     = pack_h2(n0, n1);
                hp[s2][i0 + 1] = pack_h2(n2, n3);
                ssf[s2][0] += n0 * n0 + n1 * n1;
                ssf[s2][1] += n2 * n2 + n3 * n3;
            }
        }

        /* ---- 4 residual blocks ---- */
        #pragma unroll 1
        for (int blk = 0; blk < NRB; blk++) {
            float sc[2][2];
            #pragma unroll
            for (int s2 = 0; s2 < 2; s2++)
                #pragma unroll
                for (int g = 0; g < 2; g++) {
                    float v = ssf[s2][g];
                    v += __shfl_xor_sync(0xffffffffu, v, 1);
                    v += __shfl_xor_sync(0xffffffffu, v, 2);
                    sc[s2][g] = rsqrtf(v * (1.f / HID) + RMS_EPS);
                }

            float y[2][16][4];
            #pragma unroll
            for (int s2 = 0; s2 < 2; s2++)
                #pragma unroll
                for (int j = 0; j < 16; j++)
                    y[s2][j][0] = y[s2][j][1] = y[s2][j][2] = y[s2][j][3] = 0.f;

            uint32_t lb = laneB + blk * (HID * WSTRIDE * 2);
            #pragma unroll
            for (int ks = 0; ks < 8; ks++) {
                #pragma unroll
                for (int j = 0; j < 16; j += 2) {
                    uint32_t b0, b1, b2, b3;
                    ldsm_x4(b0, b1, b2, b3,
                            lb + (uint32_t)((j * 8 * WSTRIDE + ks * 16) * 2));
                    mma16816(y[0][j],     hp[0][4*ks], hp[0][4*ks+1], hp[0][4*ks+2], hp[0][4*ks+3], b0, b1);
                    mma16816(y[0][j + 1], hp[0][4*ks], hp[0][4*ks+1], hp[0][4*ks+2], hp[0][4*ks+3], b2, b3);
                    mma16816(y[1][j],     hp[1][4*ks], hp[1][4*ks+1], hp[1][4*ks+2], hp[1][4*ks+3], b0, b1);
                    mma16816(y[1][j + 1], hp[1][4*ks], hp[1][4*ks+1], hp[1][4*ks+2], hp[1][4*ks+3], b2, b3);
                }
            }

            /* f16x2 epilogue: h += relu(s.*y + b); ss accumulated in half2 */
            const uint32_t* bb2 = brsh + blk * 64;
            uint32_t nss[2][2];
            nss[0][0] = nss[0][1] = nss[1][0] = nss[1][1] = 0u;
            #pragma unroll
            for (int j = 0; j < 16; j++) {
                float2 bb = unpack_h2(bb2[j * 4 + q]);
                int i0 = 4 * (j >> 1) + (j & 1) * 2;
                #pragma unroll
                for (int s2 = 0; s2 < 2; s2++) {
                    /* scale+bias in f32 (accurate), then pack & finish in h2 */
                    float t0 = fmaf(y[s2][j][0], sc[s2][0], bb.x);
                    float t1 = fmaf(y[s2][j][1], sc[s2][0], bb.y);
                    float t2 = fmaf(y[s2][j][2], sc[s2][1], bb.x);
                    float t3 = fmaf(y[s2][j][3], sc[s2][1], bb.y);
                    uint32_t r01 = hmax2z_u(pack_h2(t0, t1));
                    uint32_t r23 = hmax2z_u(pack_h2(t2, t3));
                    hp[s2][i0]     = hadd2_u(hp[s2][i0],     r01);
                    hp[s2][i0 + 1] = hadd2_u(hp[s2][i0 + 1], r23);
                    nss[s2][0] = hfma2_u(hp[s2][i0],     hp[s2][i0],     nss[s2][0]);
                    nss[s2][1] = hfma2_u(hp[s2][i0 + 1], hp[s2][i0 + 1], nss[s2][1]);
                }
            }
            #pragma unroll
            for (int s2 = 0; s2 < 2; s2++)
                #pragma unroll
                for (int g = 0; g < 2; g++) {
                    float2 v = unpack_h2(nss[s2][g]);
                    ssf[s2][g] = v.x + v.y;
                }
        }

        /* ---- output layer (f32) + fused segment-max ---- */
        const float2* w2 = (const float2*)wout;
        #pragma unroll
        for (int s2 = 0; s2 < 2; s2++) {
            float a0 = 0.f, a1 = 0.f;
            #pragma unroll
            for (int j = 0; j < 16; j++) {
                float2 w = w2[j * 4 + q];
                int i0 = 4 * (j >> 1) + (j & 1) * 2;
                float2 hA = unpack_h2(hp[s2][i0]);
                float2 hB = unpack_h2(hp[s2][i0 + 1]);
                a0 += hA.x * w.x + hA.y * w.y;
                a1 += hB.x * w.x + hB.y * w.y;
            }
            a0 += __shfl_xor_sync(0xffffffffu, a0, 1);
            a0 += __shfl_xor_sync(0xffffffffu, a0, 2);
            a1 += __shfl_xor_sync(0xffffffffu, a1, 1);
            a1 += __shfl_xor_sync(0xffffffffu, a1, 2);
            if (q == 0) {
                long r0 = (long)tile * TILE_M + warp * 32 + s2 * 16 + gid;
                long r1 = r0 + 8;
                float l0 = a0 + bout, l1 = a1 + bout;
                if (r0 < N_EDGES) {
                    g_logits[r0] = l0;
                    atomicMax(&g_segmax[ids[r0]], enc_f(l0));
                }
                if (r1 < N_EDGES) {
                    g_logits[r1] = l1;
                    atomicMax(&g_segmax[ids[r1]], enc_f(l1));
                }
            }
        }
    }
}

__global__ void init_kernel() {
    int i = blockIdx.x * blockDim.x + threadIdx.x;
    if (i < NUM_SEGS) { g_segmax[i] = 0u; g_segsum[i] = 0.f; }
}

__global__ void exp_kernel(const int* __restrict__ ids, float* __restrict__ out) {
    int i = blockIdx.x * blockDim.x + threadIdx.x;
    if (i < N_EDGES) {
        int s = ids[i];
        float m = dec_f(g_segmax[s]);
        float e = expf(g_logits[i] - m);
        out[i] = e;
        atomicAdd(&g_segsum[s], e);
    }
}

__global__ void norm_kernel(const int* __restrict__ ids, float* __restrict__ out) {
    int i = blockIdx.x * blockDim.x + threadIdx.x;
    if (i < N_EDGES) out[i] = out[i] / g_segsum[ids[i]];
}

extern "C" void kernel_launch(void* const* d_in, const int* in_sizes, int n_in,
                              void* d_out, int out_size)
{
    const float* ef    = (const float*)d_in[0];
    const int*   ids   = (const int*)d_in[1];
    const float* W_in  = (const float*)d_in[2];
    const float* b_in  = (const float*)d_in[3];
    const float* rms_w = (const float*)d_in[4];
    const float* W_res = (const float*)d_in[5];
    const float* b_res = (const float*)d_in[6];
    const float* W_out = (const float*)d_in[7];
    const float* b_out = (const float*)d_in[8];
    float* out = (float*)d_out;

    cudaFuncSetAttribute(mlp_kernel, cudaFuncAttributeMaxDynamicSharedMemorySize, SMEM_BYTES);

    int dev = 0, sms = 148;
    cudaGetDevice(&dev);
    cudaDeviceGetAttribute(&sms, cudaDevAttrMultiProcessorCount, dev);
    if (sms <= 0) sms = 148;

    init_kernel<<<(NUM_SEGS + 255) / 256, 256>>>();
    mlp_kernel<<<sms, NTHREADS, SMEM_BYTES>>>(ef, ids, W_in, b_in, rms_w,
                                              W_res, b_res, W_out, b_out);
    exp_kernel<<<(N_EDGES + 255) / 256, 256>>>(ids, out);
    norm_kernel<<<(N_EDGES + 255) / 256, 256>>>(ids, out);
}